// round 6
// baseline (speedup 1.0000x reference)
#include <cuda_runtime.h>
#include <cuda_bf16.h>
#include <math.h>
#include <stdint.h>

#define D_MODEL 1024
#define N_HEADS 16
#define DK      64
#define BATCH   4
#define SEQ     2048
#define M_TOTAL (BATCH * SEQ)   // 8192

// ---------------------------------------------------------------------------
// Scratch (static device globals; allocation inside kernel_launch is banned)
// ---------------------------------------------------------------------------
__device__ __nv_bfloat16 g_qhi[M_TOTAL * D_MODEL];
__device__ __nv_bfloat16 g_qlo[M_TOTAL * D_MODEL];
__device__ __nv_bfloat16 g_khi[M_TOTAL * D_MODEL];
__device__ __nv_bfloat16 g_klo[M_TOTAL * D_MODEL];
__device__ __nv_bfloat16 g_vhi[M_TOTAL * D_MODEL];
__device__ __nv_bfloat16 g_vlo[M_TOTAL * D_MODEL];
__device__ __nv_bfloat16 g_xhi[M_TOTAL * D_MODEL];
__device__ __nv_bfloat16 g_xlo[M_TOTAL * D_MODEL];
__device__ __nv_bfloat16 g_whi[D_MODEL * D_MODEL];
__device__ __nv_bfloat16 g_wlo[D_MODEL * D_MODEL];

// ---------------------------------------------------------------------------
// PTX helpers (portable sm_80+ only)
// ---------------------------------------------------------------------------
__device__ __forceinline__ uint32_t smem_u32(const void* p) {
    uint32_t a;
    asm("{ .reg .u64 t; cvta.to.shared.u64 t, %1; cvt.u32.u64 %0, t; }"
        : "=r"(a) : "l"(p));
    return a;
}
__device__ __forceinline__ void ldsm4(uint32_t* r, uint32_t addr) {
    asm volatile("ldmatrix.sync.aligned.m8n8.x4.shared.b16 {%0,%1,%2,%3}, [%4];"
                 : "=r"(r[0]), "=r"(r[1]), "=r"(r[2]), "=r"(r[3]) : "r"(addr));
}
__device__ __forceinline__ void ldsm4t(uint32_t* r, uint32_t addr) {
    asm volatile("ldmatrix.sync.aligned.m8n8.x4.trans.shared.b16 {%0,%1,%2,%3}, [%4];"
                 : "=r"(r[0]), "=r"(r[1]), "=r"(r[2]), "=r"(r[3]) : "r"(addr));
}
__device__ __forceinline__ void mma_bf16(float* c, const uint32_t* a,
                                         uint32_t b0, uint32_t b1) {
    asm volatile(
        "mma.sync.aligned.m16n8k16.row.col.f32.bf16.bf16.f32 "
        "{%0,%1,%2,%3}, {%4,%5,%6,%7}, {%8,%9}, {%0,%1,%2,%3};"
        : "+f"(c[0]), "+f"(c[1]), "+f"(c[2]), "+f"(c[3])
        : "r"(a[0]), "r"(a[1]), "r"(a[2]), "r"(a[3]), "r"(b0), "r"(b1));
}
#define CP_ASYNC16(dst, src) \
    asm volatile("cp.async.cg.shared.global [%0], [%1], 16;" :: "r"(dst), "l"(src))
#define CP_COMMIT()  asm volatile("cp.async.commit_group;" ::: "memory")
#define CP_WAIT1()   asm volatile("cp.async.wait_group 1;" ::: "memory")

// pack hi-bf16 halves of two floats (truncation split): lo half <- a, hi half <- b
__device__ __forceinline__ uint32_t pack_hi(float a, float b) {
    uint32_t r;
    asm("prmt.b32 %0, %1, %2, 0x7632;" : "=r"(r)
        : "r"(__float_as_uint(a)), "r"(__float_as_uint(b)));
    return r;
}
__device__ __forceinline__ float hi_part(float a) {
    return __uint_as_float(__float_as_uint(a) & 0xFFFF0000u);
}
// pack bf16x2 from two floats (RN): lo half <- a, hi half <- b
__device__ __forceinline__ uint32_t pack_rn(float a, float b) {
    uint32_t r;
    asm("cvt.rn.bf16x2.f32 %0, %1, %2;" : "=r"(r) : "f"(b), "f"(a));
    return r;
}

// ---------------------------------------------------------------------------
// fp32 -> (bf16 hi, bf16 lo) split
// ---------------------------------------------------------------------------
__global__ __launch_bounds__(256) void split_kernel(
    const float* __restrict__ x, __nv_bfloat16* __restrict__ hi,
    __nv_bfloat16* __restrict__ lo, int n4)
{
    int i = blockIdx.x * blockDim.x + threadIdx.x;
    if (i >= n4) return;
    float4 v = ((const float4*)x)[i];
    uint32_t* hp = (uint32_t*)hi;
    uint32_t* lp = (uint32_t*)lo;
    hp[2 * i]     = pack_hi(v.x, v.y);
    hp[2 * i + 1] = pack_hi(v.z, v.w);
    lp[2 * i]     = pack_rn(v.x - hi_part(v.x), v.y - hi_part(v.y));
    lp[2 * i + 1] = pack_rn(v.z - hi_part(v.z), v.w - hi_part(v.w));
}

// ---------------------------------------------------------------------------
// mma.sync NT GEMM with bias, bf16 2-term split (hi*hi + hi*lo + lo*hi):
//   out[m,n] = sum_k X[m,k]*W[n,k] + bias[n]
// CTA 128x128, 8 warps (2Mx4N), warp tile 64x32. 3-stage cp.async pipeline,
// CUTLASS ordering: [issue load c+2] [compute c] [wait<1>] [one barrier].
// ---------------------------------------------------------------------------
#define TM 128
#define TN 128
#define KC 64
#define NCHUNK (D_MODEL / KC)          // 16
#define STAGE_BYTES (4 * 128 * 128)    // Ahi|Alo|Bhi|Blo, 16KB each = 64KB
#define NSTAGE 3
#define SM_TOTAL (NSTAGE * STAGE_BYTES)  // 192KB

__global__ __launch_bounds__(256, 1) void gemm_mma(
    const __nv_bfloat16* __restrict__ Xhi, const __nv_bfloat16* __restrict__ Xlo,
    const __nv_bfloat16* __restrict__ Whi, const __nv_bfloat16* __restrict__ Wlo,
    const float* __restrict__ bias, float* __restrict__ outf,
    __nv_bfloat16* __restrict__ ohi, __nv_bfloat16* __restrict__ olo)
{
    extern __shared__ __align__(1024) char smem[];
    const uint32_t smem_base = smem_u32(smem);
    const int tid  = threadIdx.x;
    const int wid  = tid >> 5;
    const int lane = tid & 31;
    const int wm   = wid & 1;
    const int wn   = wid >> 1;
    const int bm = blockIdx.y * TM;
    const int bn = blockIdx.x * TN;

    const __nv_bfloat16* srcs[4];
    srcs[0] = Xhi + (size_t)bm * D_MODEL;
    srcs[1] = Xlo + (size_t)bm * D_MODEL;
    srcs[2] = Whi + (size_t)bn * D_MODEL;
    srcs[3] = Wlo + (size_t)bn * D_MODEL;

    const int a_row_off  = ((lane >> 3) & 1) * 8 + (lane & 7);
    const int a_unit_off = lane >> 4;
    const int b_row_off  = ((lane >> 4) & 1) * 8 + (lane & 7);
    const int b_unit_off = (lane >> 3) & 1;

    float acc[4][4][4];
#pragma unroll
    for (int mt = 0; mt < 4; mt++)
#pragma unroll
        for (int nt = 0; nt < 4; nt++)
#pragma unroll
            for (int j = 0; j < 4; j++) acc[mt][nt][j] = 0.f;

    auto stage_load = [&](int buf, int c) {
        const uint32_t stage = smem_base + buf * STAGE_BYTES;
#pragma unroll
        for (int s = 0; s < 4; ++s) {
#pragma unroll
            for (int i = 0; i < 4; ++i) {
                int idx = i * 256 + tid;
                int row = idx >> 3, u = idx & 7;
                const void* src = srcs[s] + (size_t)row * D_MODEL + c * KC + u * 8;
                uint32_t dst = stage + s * 16384 + row * 128 + ((u ^ (row & 7)) << 4);
                CP_ASYNC16(dst, src);
            }
        }
        CP_COMMIT();
    };

    // prologue: stages 0,1 in flight; wait for 0; one barrier
    stage_load(0, 0);
    stage_load(1, 1);
    CP_WAIT1();
    __syncthreads();

#pragma unroll 1
    for (int c = 0; c < NCHUNK; ++c) {
        // issue load for chunk c+2 into slot (c+2)%3 (freed by prev barrier)
        if (c + 2 < NCHUNK) stage_load((c + 2) % NSTAGE, c + 2);
        else                CP_COMMIT();   // empty group keeps wait<1> math exact

        const uint32_t stage = smem_base + (c % NSTAGE) * STAGE_BYTES;
        const uint32_t Ah = stage;
        const uint32_t Al = stage + 16384;
        const uint32_t Bh = stage + 32768;
        const uint32_t Bl = stage + 49152;

#pragma unroll
        for (int ks = 0; ks < 4; ++ks) {
            uint32_t ah[4][4], al[4][4], bh[2][4], bl[2][4];
#pragma unroll
            for (int mt = 0; mt < 4; ++mt) {
                int row  = wm * 64 + mt * 16 + a_row_off;
                int unit = ks * 2 + a_unit_off;
                uint32_t off = row * 128 + ((unit ^ (row & 7)) << 4);
                ldsm4(ah[mt], Ah + off);
                ldsm4(al[mt], Al + off);
            }
#pragma unroll
            for (int nh = 0; nh < 2; ++nh) {
                int row  = wn * 32 + nh * 16 + b_row_off;
                int unit = ks * 2 + b_unit_off;
                uint32_t off = row * 128 + ((unit ^ (row & 7)) << 4);
                ldsm4(bh[nh], Bh + off);
                ldsm4(bl[nh], Bl + off);
            }
#pragma unroll
            for (int mt = 0; mt < 4; ++mt) {
#pragma unroll
                for (int nt = 0; nt < 4; ++nt) {
                    const int nh = nt >> 1, p = (nt & 1) * 2;
                    mma_bf16(acc[mt][nt], ah[mt], bh[nh][p], bh[nh][p + 1]);
                    mma_bf16(acc[mt][nt], ah[mt], bl[nh][p], bl[nh][p + 1]);
                    mma_bf16(acc[mt][nt], al[mt], bh[nh][p], bh[nh][p + 1]);
                }
            }
        }
        CP_WAIT1();          // chunk c+1 resident for next iteration
        __syncthreads();     // one barrier per chunk
    }

    const int grow = lane >> 2;
    const int gcol = (lane & 3) * 2;
#pragma unroll
    for (int mt = 0; mt < 4; ++mt) {
#pragma unroll
        for (int nt = 0; nt < 4; ++nt) {
            const int m0 = bm + wm * 64 + mt * 16 + grow;
            const int n0 = bn + wn * 32 + nt * 8 + gcol;
            const float b0 = bias[n0], b1 = bias[n0 + 1];
            float v00 = acc[mt][nt][0] + b0, v01 = acc[mt][nt][1] + b1;
            float v10 = acc[mt][nt][2] + b0, v11 = acc[mt][nt][3] + b1;
            if (outf) {
                *(float2*)&outf[(size_t)m0 * D_MODEL + n0]       = make_float2(v00, v01);
                *(float2*)&outf[(size_t)(m0 + 8) * D_MODEL + n0] = make_float2(v10, v11);
            } else {
                *(uint32_t*)&ohi[(size_t)m0 * D_MODEL + n0] = pack_hi(v00, v01);
                *(uint32_t*)&olo[(size_t)m0 * D_MODEL + n0] =
                    pack_rn(v00 - hi_part(v00), v01 - hi_part(v01));
                *(uint32_t*)&ohi[(size_t)(m0 + 8) * D_MODEL + n0] = pack_hi(v10, v11);
                *(uint32_t*)&olo[(size_t)(m0 + 8) * D_MODEL + n0] =
                    pack_rn(v10 - hi_part(v10), v11 - hi_part(v11));
            }
        }
    }
}

// ---------------------------------------------------------------------------
// Causal flash attention on mma.sync, bf16 hi/lo split for QK^T and PV.
// Block: 128 queries, 8 warps. Key tiles of 64, 3-stage cp.async pipeline.
// Heavy (large-qb) blocks scheduled first via reversed block index.
// ---------------------------------------------------------------------------
#define AQ 128
#define AKT 64
#define A_SQ_LO    16384
#define A_STAGES   32768
#define A_STAGE_SZ 32768
#define A_NSTAGE   3
#define A_SM_TOTAL (A_STAGES + A_NSTAGE * A_STAGE_SZ)   // 131072

__global__ __launch_bounds__(256, 1) void attn_mma(
    const __nv_bfloat16* __restrict__ qhi, const __nv_bfloat16* __restrict__ qlo,
    const __nv_bfloat16* __restrict__ khi, const __nv_bfloat16* __restrict__ klo,
    const __nv_bfloat16* __restrict__ vhi, const __nv_bfloat16* __restrict__ vlo,
    __nv_bfloat16* __restrict__ ohi, __nv_bfloat16* __restrict__ olo)
{
    extern __shared__ __align__(1024) char smem[];
    const uint32_t smem_base = smem_u32(smem);
    const int tid  = threadIdx.x;
    const int w    = tid >> 5;
    const int lane = tid & 31;
    const int qb = gridDim.x - 1 - blockIdx.x;   // heavy blocks first
    const int h  = blockIdx.y;
    const int b  = blockIdx.z;

    const int a_row_off  = ((lane >> 3) & 1) * 8 + (lane & 7);
    const int a_unit_off = lane >> 4;
    const int b_row_off  = ((lane >> 4) & 1) * 8 + (lane & 7);
    const int b_unit_off = (lane >> 3) & 1;
    const int grow = lane >> 2;
    const int gcol = (lane & 3) * 2;

    const int KT = 2 * qb + 2;

    auto q_load = [&]() {
#pragma unroll
        for (int i = 0; i < 8; ++i) {
            int idx = i * 256 + tid;
            int t = idx >> 10, row = (idx >> 3) & 127, u = idx & 7;
            const __nv_bfloat16* src =
                (t ? qlo : qhi) + (size_t)(b * SEQ + qb * AQ + row) * D_MODEL + h * DK + u * 8;
            uint32_t dst = smem_base + t * 16384 + row * 128 + ((u ^ (row & 7)) << 4);
            CP_ASYNC16(dst, src);
        }
        CP_COMMIT();
    };
    auto stage_load = [&](int s, int kt) {
        const uint32_t base = smem_base + A_STAGES + s * A_STAGE_SZ;
#pragma unroll
        for (int i = 0; i < 8; ++i) {
            int idx = i * 256 + tid;
            int t = idx >> 9, row = (idx >> 3) & 63, u = idx & 7;
            const __nv_bfloat16* arr = (t == 0) ? khi : (t == 1) ? klo : (t == 2) ? vhi : vlo;
            const __nv_bfloat16* src =
                arr + (size_t)(b * SEQ + kt * AKT + row) * D_MODEL + h * DK + u * 8;
            uint32_t dst = base + t * 8192 + row * 128 + ((u ^ (row & 7)) << 4);
            CP_ASYNC16(dst, src);
        }
        CP_COMMIT();
    };

    // prologue: q + stages 0,1 in flight; wait for q + stage0; one barrier
    q_load();
    stage_load(0, 0);
    stage_load(1, 1);
    CP_WAIT1();
    __syncthreads();

    uint32_t qh[4][4], ql[4][4];
#pragma unroll
    for (int ks = 0; ks < 4; ++ks) {
        int row  = w * 16 + a_row_off;
        int unit = ks * 2 + a_unit_off;
        uint32_t off = row * 128 + ((unit ^ (row & 7)) << 4);
        ldsm4(qh[ks], smem_base + off);
        ldsm4(ql[ks], smem_base + A_SQ_LO + off);
    }

    float of[8][4];
#pragma unroll
    for (int nt = 0; nt < 8; ++nt)
#pragma unroll
        for (int j = 0; j < 4; ++j) of[nt][j] = 0.f;
    float m0 = -1e30f, m1 = -1e30f, l0 = 0.f, l1 = 0.f;

    const int q0g = qb * AQ + w * 16 + grow;
    const int q1g = q0g + 8;
    const int qmax_warp = qb * AQ + w * 16 + 15;
    const float NEG_INF = __int_as_float(0xff800000);

#pragma unroll 1
    for (int kt = 0; kt < KT; ++kt) {
        if (kt + 2 < KT) stage_load((kt + 2) % A_NSTAGE, kt + 2);
        else             CP_COMMIT();

        if (kt * AKT <= qmax_warp) {
            const uint32_t Kh = smem_base + A_STAGES + (kt % A_NSTAGE) * A_STAGE_SZ;
            const uint32_t Kl = Kh + 8192;
            const uint32_t Vh = Kh + 16384;
            const uint32_t Vl = Kh + 24576;

            // ---- S = Q K^T (3-term split) ----
            float sf[8][4];
#pragma unroll
            for (int nt = 0; nt < 8; ++nt)
#pragma unroll
                for (int j = 0; j < 4; ++j) sf[nt][j] = 0.f;

#pragma unroll
            for (int ks = 0; ks < 4; ++ks) {
#pragma unroll
                for (int nh = 0; nh < 4; ++nh) {
                    int row  = nh * 16 + b_row_off;
                    int unit = ks * 2 + b_unit_off;
                    uint32_t off = row * 128 + ((unit ^ (row & 7)) << 4);
                    uint32_t kh[4], kl[4];
                    ldsm4(kh, Kh + off);
                    ldsm4(kl, Kl + off);
                    mma_bf16(sf[2 * nh],     qh[ks], kh[0], kh[1]);
                    mma_bf16(sf[2 * nh],     qh[ks], kl[0], kl[1]);
                    mma_bf16(sf[2 * nh],     ql[ks], kh[0], kh[1]);
                    mma_bf16(sf[2 * nh + 1], qh[ks], kh[2], kh[3]);
                    mma_bf16(sf[2 * nh + 1], qh[ks], kl[2], kl[3]);
                    mma_bf16(sf[2 * nh + 1], ql[ks], kh[2], kh[3]);
                }
            }

            // ---- scale + causal mask ----
            const bool needmask = (kt >= 2 * qb);
#pragma unroll
            for (int nt = 0; nt < 8; ++nt) {
#pragma unroll
                for (int j = 0; j < 4; ++j) sf[nt][j] *= 0.125f;
                if (needmask) {
                    int c0 = kt * AKT + nt * 8 + gcol;
                    if (c0     > q0g) sf[nt][0] = NEG_INF;
                    if (c0 + 1 > q0g) sf[nt][1] = NEG_INF;
                    if (c0     > q1g) sf[nt][2] = NEG_INF;
                    if (c0 + 1 > q1g) sf[nt][3] = NEG_INF;
                }
            }

            // ---- online softmax ----
            float tm0 = sf[0][0], tm1 = sf[0][2];
#pragma unroll
            for (int nt = 0; nt < 8; ++nt) {
                tm0 = fmaxf(tm0, fmaxf(sf[nt][0], sf[nt][1]));
                tm1 = fmaxf(tm1, fmaxf(sf[nt][2], sf[nt][3]));
            }
            tm0 = fmaxf(tm0, __shfl_xor_sync(0xffffffffu, tm0, 1));
            tm0 = fmaxf(tm0, __shfl_xor_sync(0xffffffffu, tm0, 2));
            tm1 = fmaxf(tm1, __shfl_xor_sync(0xffffffffu, tm1, 1));
            tm1 = fmaxf(tm1, __shfl_xor_sync(0xffffffffu, tm1, 2));

            const float m0n = fmaxf(m0, tm0);
            const float m1n = fmaxf(m1, tm1);
            const float sc0 = __expf(m0 - m0n);
            const float sc1 = __expf(m1 - m1n);
            l0 *= sc0; l1 *= sc1;
#pragma unroll
            for (int nt = 0; nt < 8; ++nt) {
                of[nt][0] *= sc0; of[nt][1] *= sc0;
                of[nt][2] *= sc1; of[nt][3] *= sc1;
            }
            m0 = m0n; m1 = m1n;

            float p[8][4];
#pragma unroll
            for (int nt = 0; nt < 8; ++nt) {
                p[nt][0] = __expf(sf[nt][0] - m0n);
                p[nt][1] = __expf(sf[nt][1] - m0n);
                p[nt][2] = __expf(sf[nt][2] - m1n);
                p[nt][3] = __expf(sf[nt][3] - m1n);
                l0 += p[nt][0] + p[nt][1];
                l1 += p[nt][2] + p[nt][3];
            }

            // ---- pack P into A-frags ----
            uint32_t pah[4][4], pal[4][4];
#pragma unroll
            for (int j = 0; j < 4; ++j) {
                pah[j][0] = pack_hi(p[2 * j][0],     p[2 * j][1]);
                pah[j][1] = pack_hi(p[2 * j][2],     p[2 * j][3]);
                pah[j][2] = pack_hi(p[2 * j + 1][0], p[2 * j + 1][1]);
                pah[j][3] = pack_hi(p[2 * j + 1][2], p[2 * j + 1][3]);
                pal[j][0] = pack_rn(p[2 * j][0] - hi_part(p[2 * j][0]),
                                    p[2 * j][1] - hi_part(p[2 * j][1]));
                pal[j][1] = pack_rn(p[2 * j][2] - hi_part(p[2 * j][2]),
                                    p[2 * j][3] - hi_part(p[2 * j][3]));
                pal[j][2] = pack_rn(p[2 * j + 1][0] - hi_part(p[2 * j + 1][0]),
                                    p[2 * j + 1][1] - hi_part(p[2 * j + 1][1]));
                pal[j][3] = pack_rn(p[2 * j + 1][2] - hi_part(p[2 * j + 1][2]),
                                    p[2 * j + 1][3] - hi_part(p[2 * j + 1][3]));
            }

            // ---- O += P V (3-term split), V via ldmatrix.trans ----
            const int vrow_off = ((lane >> 3) & 1) * 8 + (lane & 7);
            const int vunit_off = (lane >> 4) & 1;
#pragma unroll
            for (int ks = 0; ks < 4; ++ks) {
#pragma unroll
                for (int nh = 0; nh < 4; ++nh) {
                    int row  = ks * 16 + vrow_off;
                    int unit = nh * 2 + vunit_off;
                    uint32_t off = row * 128 + ((unit ^ (row & 7)) << 4);
                    uint32_t vh[4], vl[4];
                    ldsm4t(vh, Vh + off);
                    ldsm4t(vl, Vl + off);
                    mma_bf16(of[2 * nh],     pah[ks], vh[0], vh[1]);
                    mma_bf16(of[2 * nh],     pah[ks], vl[0], vl[1]);
                    mma_bf16(of[2 * nh],     pal[ks], vh[0], vh[1]);
                    mma_bf16(of[2 * nh + 1], pah[ks], vh[2], vh[3]);
                    mma_bf16(of[2 * nh + 1], pah[ks], vl[2], vl[3]);
                    mma_bf16(of[2 * nh + 1], pal[ks], vh[2], vh[3]);
                }
            }
        }
        CP_WAIT1();
        __syncthreads();
    }

    // ---- epilogue ----
    l0 += __shfl_xor_sync(0xffffffffu, l0, 1);
    l0 += __shfl_xor_sync(0xffffffffu, l0, 2);
    l1 += __shfl_xor_sync(0xffffffffu, l1, 1);
    l1 += __shfl_xor_sync(0xffffffffu, l1, 2);
    const float inv0 = 1.f / l0;
    const float inv1 = 1.f / l1;

    const size_t r0 = (size_t)(b * SEQ + q0g);
    const size_t r1 = (size_t)(b * SEQ + q1g);
#pragma unroll
    for (int nt = 0; nt < 8; ++nt) {
        const int col = h * DK + nt * 8 + gcol;
        float v00 = of[nt][0] * inv0, v01 = of[nt][1] * inv0;
        float v10 = of[nt][2] * inv1, v11 = of[nt][3] * inv1;
        *(uint32_t*)&ohi[r0 * D_MODEL + col] = pack_hi(v00, v01);
        *(uint32_t*)&olo[r0 * D_MODEL + col] =
            pack_rn(v00 - hi_part(v00), v01 - hi_part(v01));
        *(uint32_t*)&ohi[r1 * D_MODEL + col] = pack_hi(v10, v11);
        *(uint32_t*)&olo[r1 * D_MODEL + col] =
            pack_rn(v10 - hi_part(v10), v11 - hi_part(v11));
    }
}

// ---------------------------------------------------------------------------
// Launch
// Inputs (metadata order): Q, K, V, mask, W_q, b_q, W_k, b_k, W_v, b_v, W_o, b_o
// ---------------------------------------------------------------------------
extern "C" void kernel_launch(void* const* d_in, const int* in_sizes, int n_in,
                              void* d_out, int out_size)
{
    const float* Q   = (const float*)d_in[0];
    const float* K   = (const float*)d_in[1];
    const float* V   = (const float*)d_in[2];
    const float* W_q = (const float*)d_in[4];
    const float* b_q = (const float*)d_in[5];
    const float* W_k = (const float*)d_in[6];
    const float* b_k = (const float*)d_in[7];
    const float* W_v = (const float*)d_in[8];
    const float* b_v = (const float*)d_in[9];
    const float* W_o = (const float*)d_in[10];
    const float* b_o = (const float*)d_in[11];
    float* out = (float*)d_out;

    __nv_bfloat16 *qhi, *qlo, *khi, *klo, *vhi, *vlo, *xhi, *xlo, *whi, *wlo;
    cudaGetSymbolAddress((void**)&qhi, g_qhi);
    cudaGetSymbolAddress((void**)&qlo, g_qlo);
    cudaGetSymbolAddress((void**)&khi, g_khi);
    cudaGetSymbolAddress((void**)&klo, g_klo);
    cudaGetSymbolAddress((void**)&vhi, g_vhi);
    cudaGetSymbolAddress((void**)&vlo, g_vlo);
    cudaGetSymbolAddress((void**)&xhi, g_xhi);
    cudaGetSymbolAddress((void**)&xlo, g_xlo);
    cudaGetSymbolAddress((void**)&whi, g_whi);
    cudaGetSymbolAddress((void**)&wlo, g_wlo);

    cudaFuncSetAttribute(gemm_mma, cudaFuncAttributeMaxDynamicSharedMemorySize, SM_TOTAL);
    cudaFuncSetAttribute(attn_mma, cudaFuncAttributeMaxDynamicSharedMemorySize, A_SM_TOTAL);

    const int nX4 = M_TOTAL * D_MODEL / 4;
    const int nW4 = D_MODEL * D_MODEL / 4;
    const int SPLIT_B = 256;
    dim3 gX((nX4 + SPLIT_B - 1) / SPLIT_B);
    dim3 gW((nW4 + SPLIT_B - 1) / SPLIT_B);
    dim3 gGemm(D_MODEL / TN, M_TOTAL / TM);   // (8, 64)

    // Q projection -> qhi/qlo
    split_kernel<<<gX, SPLIT_B>>>(Q, xhi, xlo, nX4);
    split_kernel<<<gW, SPLIT_B>>>(W_q, whi, wlo, nW4);
    gemm_mma<<<gGemm, 256, SM_TOTAL>>>(xhi, xlo, whi, wlo, b_q, nullptr, qhi, qlo);
    // K projection -> khi/klo
    split_kernel<<<gX, SPLIT_B>>>(K, xhi, xlo, nX4);
    split_kernel<<<gW, SPLIT_B>>>(W_k, whi, wlo, nW4);
    gemm_mma<<<gGemm, 256, SM_TOTAL>>>(xhi, xlo, whi, wlo, b_k, nullptr, khi, klo);
    // V projection -> vhi/vlo
    split_kernel<<<gX, SPLIT_B>>>(V, xhi, xlo, nX4);
    split_kernel<<<gW, SPLIT_B>>>(W_v, whi, wlo, nW4);
    gemm_mma<<<gGemm, 256, SM_TOTAL>>>(xhi, xlo, whi, wlo, b_v, nullptr, vhi, vlo);

    // attention -> writes xhi/xlo (input of O projection)
    dim3 gAttn(SEQ / AQ, N_HEADS, BATCH);     // (16, 16, 4)
    attn_mma<<<gAttn, 256, A_SM_TOTAL>>>(qhi, qlo, khi, klo, vhi, vlo, xhi, xlo);

    // O projection -> fp32 out
    split_kernel<<<gW, SPLIT_B>>>(W_o, whi, wlo, nW4);
    gemm_mma<<<gGemm, 256, SM_TOTAL>>>(xhi, xlo, whi, wlo, b_o, out, nullptr, nullptr);
}

// round 7
// speedup vs baseline: 1.0354x; 1.0354x over previous
#include <cuda_runtime.h>
#include <cuda_bf16.h>
#include <math.h>
#include <stdint.h>

#define D_MODEL 1024
#define N_HEADS 16
#define DK      64
#define BATCH   4
#define SEQ     2048
#define M_TOTAL (BATCH * SEQ)   // 8192
#define MD      ((size_t)M_TOTAL * D_MODEL)
#define DD      ((size_t)D_MODEL * D_MODEL)

// ---------------------------------------------------------------------------
// Scratch (static device globals; allocation inside kernel_launch is banned)
// g_inhi/lo : bf16 splits of the three GEMM inputs (z=0:Q,1:K,2:V).
//             Slot 0 is reused for the attention output (O-GEMM input).
// g_prjhi/lo: projected q (z=0), k (z=1), v (z=2), as bf16 hi/lo.
// g_whi4/lo4: weight splits, z=0:W_q 1:W_k 2:W_v 3:W_o.
// ---------------------------------------------------------------------------
__device__ __nv_bfloat16 g_inhi [3 * M_TOTAL * D_MODEL];
__device__ __nv_bfloat16 g_inlo [3 * M_TOTAL * D_MODEL];
__device__ __nv_bfloat16 g_prjhi[3 * M_TOTAL * D_MODEL];
__device__ __nv_bfloat16 g_prjlo[3 * M_TOTAL * D_MODEL];
__device__ __nv_bfloat16 g_whi4 [4 * D_MODEL * D_MODEL];
__device__ __nv_bfloat16 g_wlo4 [4 * D_MODEL * D_MODEL];

// ---------------------------------------------------------------------------
// PTX helpers (portable sm_80+ only)
// ---------------------------------------------------------------------------
__device__ __forceinline__ uint32_t smem_u32(const void* p) {
    uint32_t a;
    asm("{ .reg .u64 t; cvta.to.shared.u64 t, %1; cvt.u32.u64 %0, t; }"
        : "=r"(a) : "l"(p));
    return a;
}
__device__ __forceinline__ void ldsm4(uint32_t* r, uint32_t addr) {
    asm volatile("ldmatrix.sync.aligned.m8n8.x4.shared.b16 {%0,%1,%2,%3}, [%4];"
                 : "=r"(r[0]), "=r"(r[1]), "=r"(r[2]), "=r"(r[3]) : "r"(addr));
}
__device__ __forceinline__ void ldsm4t(uint32_t* r, uint32_t addr) {
    asm volatile("ldmatrix.sync.aligned.m8n8.x4.trans.shared.b16 {%0,%1,%2,%3}, [%4];"
                 : "=r"(r[0]), "=r"(r[1]), "=r"(r[2]), "=r"(r[3]) : "r"(addr));
}
__device__ __forceinline__ void mma_bf16(float* c, const uint32_t* a,
                                         uint32_t b0, uint32_t b1) {
    asm volatile(
        "mma.sync.aligned.m16n8k16.row.col.f32.bf16.bf16.f32 "
        "{%0,%1,%2,%3}, {%4,%5,%6,%7}, {%8,%9}, {%0,%1,%2,%3};"
        : "+f"(c[0]), "+f"(c[1]), "+f"(c[2]), "+f"(c[3])
        : "r"(a[0]), "r"(a[1]), "r"(a[2]), "r"(a[3]), "r"(b0), "r"(b1));
}
#define CP_ASYNC16(dst, src) \
    asm volatile("cp.async.cg.shared.global [%0], [%1], 16;" :: "r"(dst), "l"(src))
#define CP_COMMIT()  asm volatile("cp.async.commit_group;" ::: "memory")
#define CP_WAIT1()   asm volatile("cp.async.wait_group 1;" ::: "memory")

// pack hi-bf16 halves of two floats (truncation split): lo half <- a, hi half <- b
__device__ __forceinline__ uint32_t pack_hi(float a, float b) {
    uint32_t r;
    asm("prmt.b32 %0, %1, %2, 0x7632;" : "=r"(r)
        : "r"(__float_as_uint(a)), "r"(__float_as_uint(b)));
    return r;
}
__device__ __forceinline__ float hi_part(float a) {
    return __uint_as_float(__float_as_uint(a) & 0xFFFF0000u);
}
// pack bf16x2 from two floats (RN): lo half <- a, hi half <- b
__device__ __forceinline__ uint32_t pack_rn(float a, float b) {
    uint32_t r;
    asm("cvt.rn.bf16x2.f32 %0, %1, %2;" : "=r"(r) : "f"(b), "f"(a));
    return r;
}

// ---------------------------------------------------------------------------
// Fused fp32 -> (bf16 hi, bf16 lo) splits.
// split3: three activation tensors (Q,K,V inputs), z selects input + out slot.
// split4: four weight matrices, z selects.
// ---------------------------------------------------------------------------
__device__ __forceinline__ void split_one(const float* __restrict__ x,
                                          __nv_bfloat16* __restrict__ hi,
                                          __nv_bfloat16* __restrict__ lo, int i) {
    float4 v = ((const float4*)x)[i];
    uint32_t* hp = (uint32_t*)hi;
    uint32_t* lp = (uint32_t*)lo;
    hp[2 * i]     = pack_hi(v.x, v.y);
    hp[2 * i + 1] = pack_hi(v.z, v.w);
    lp[2 * i]     = pack_rn(v.x - hi_part(v.x), v.y - hi_part(v.y));
    lp[2 * i + 1] = pack_rn(v.z - hi_part(v.z), v.w - hi_part(v.w));
}

__global__ __launch_bounds__(256) void split3_kernel(
    const float* __restrict__ x0, const float* __restrict__ x1,
    const float* __restrict__ x2,
    __nv_bfloat16* __restrict__ hiB, __nv_bfloat16* __restrict__ loB, int n4)
{
    int i = blockIdx.x * blockDim.x + threadIdx.x;
    if (i >= n4) return;
    int z = blockIdx.z;
    const float* x = (z == 0) ? x0 : (z == 1) ? x1 : x2;
    split_one(x, hiB + (size_t)z * MD, loB + (size_t)z * MD, i);
}

__global__ __launch_bounds__(256) void split4_kernel(
    const float* __restrict__ w0, const float* __restrict__ w1,
    const float* __restrict__ w2, const float* __restrict__ w3,
    __nv_bfloat16* __restrict__ hiB, __nv_bfloat16* __restrict__ loB, int n4)
{
    int i = blockIdx.x * blockDim.x + threadIdx.x;
    if (i >= n4) return;
    int z = blockIdx.z;
    const float* w = (z == 0) ? w0 : (z == 1) ? w1 : (z == 2) ? w2 : w3;
    split_one(w, hiB + (size_t)z * DD, loB + (size_t)z * DD, i);
}

// ---------------------------------------------------------------------------
// mma.sync NT GEMM with bias, bf16 2-term split (hi*hi + hi*lo + lo*hi):
//   out[m,n] = sum_k X[m,k]*W[n,k] + bias[n]
// CTA 128x128, 8 warps (2Mx4N). 3-stage cp.async pipeline.
// blockIdx.z selects input slot / weight slot / bias / output slot, so the
// three QKV projections run as ONE launch (better wave fill).
// ---------------------------------------------------------------------------
#define TM 128
#define TN 128
#define KC 64
#define NCHUNK (D_MODEL / KC)          // 16
#define STAGE_BYTES (4 * 128 * 128)    // Ahi|Alo|Bhi|Blo, 16KB each = 64KB
#define NSTAGE 3
#define SM_TOTAL (NSTAGE * STAGE_BYTES)  // 192KB

__global__ __launch_bounds__(256, 1) void gemm_mma(
    const __nv_bfloat16* __restrict__ XhiB, const __nv_bfloat16* __restrict__ XloB,
    const __nv_bfloat16* __restrict__ WhiB, const __nv_bfloat16* __restrict__ WloB,
    const float* __restrict__ bias0, const float* __restrict__ bias1,
    const float* __restrict__ bias2,
    float* __restrict__ outf,
    __nv_bfloat16* __restrict__ ohiB, __nv_bfloat16* __restrict__ oloB)
{
    extern __shared__ __align__(1024) char smem[];
    const uint32_t smem_base = smem_u32(smem);
    const int tid  = threadIdx.x;
    const int wid  = tid >> 5;
    const int lane = tid & 31;
    const int wm   = wid & 1;
    const int wn   = wid >> 1;
    const int bm = blockIdx.y * TM;
    const int bn = blockIdx.x * TN;
    const int z  = blockIdx.z;

    const float* bias = (z == 0) ? bias0 : (z == 1) ? bias1 : bias2;
    const __nv_bfloat16* Xhi = XhiB + (size_t)z * MD;
    const __nv_bfloat16* Xlo = XloB + (size_t)z * MD;
    const __nv_bfloat16* Whi = WhiB + (size_t)z * DD;
    const __nv_bfloat16* Wlo = WloB + (size_t)z * DD;

    const __nv_bfloat16* srcs[4];
    srcs[0] = Xhi + (size_t)bm * D_MODEL;
    srcs[1] = Xlo + (size_t)bm * D_MODEL;
    srcs[2] = Whi + (size_t)bn * D_MODEL;
    srcs[3] = Wlo + (size_t)bn * D_MODEL;

    const int a_row_off  = ((lane >> 3) & 1) * 8 + (lane & 7);
    const int a_unit_off = lane >> 4;
    const int b_row_off  = ((lane >> 4) & 1) * 8 + (lane & 7);
    const int b_unit_off = (lane >> 3) & 1;

    float acc[4][4][4];
#pragma unroll
    for (int mt = 0; mt < 4; mt++)
#pragma unroll
        for (int nt = 0; nt < 4; nt++)
#pragma unroll
            for (int j = 0; j < 4; j++) acc[mt][nt][j] = 0.f;

    auto stage_load = [&](int buf, int c) {
        const uint32_t stage = smem_base + buf * STAGE_BYTES;
#pragma unroll
        for (int s = 0; s < 4; ++s) {
#pragma unroll
            for (int i = 0; i < 4; ++i) {
                int idx = i * 256 + tid;
                int row = idx >> 3, u = idx & 7;
                const void* src = srcs[s] + (size_t)row * D_MODEL + c * KC + u * 8;
                uint32_t dst = stage + s * 16384 + row * 128 + ((u ^ (row & 7)) << 4);
                CP_ASYNC16(dst, src);
            }
        }
        CP_COMMIT();
    };

    stage_load(0, 0);
    stage_load(1, 1);
    CP_WAIT1();
    __syncthreads();

#pragma unroll 1
    for (int c = 0; c < NCHUNK; ++c) {
        if (c + 2 < NCHUNK) stage_load((c + 2) % NSTAGE, c + 2);
        else                CP_COMMIT();   // empty group keeps wait<1> math exact

        const uint32_t stage = smem_base + (c % NSTAGE) * STAGE_BYTES;
        const uint32_t Ah = stage;
        const uint32_t Al = stage + 16384;
        const uint32_t Bh = stage + 32768;
        const uint32_t Bl = stage + 49152;

#pragma unroll
        for (int ks = 0; ks < 4; ++ks) {
            uint32_t ah[4][4], al[4][4], bh[2][4], bl[2][4];
#pragma unroll
            for (int mt = 0; mt < 4; ++mt) {
                int row  = wm * 64 + mt * 16 + a_row_off;
                int unit = ks * 2 + a_unit_off;
                uint32_t off = row * 128 + ((unit ^ (row & 7)) << 4);
                ldsm4(ah[mt], Ah + off);
                ldsm4(al[mt], Al + off);
            }
#pragma unroll
            for (int nh = 0; nh < 2; ++nh) {
                int row  = wn * 32 + nh * 16 + b_row_off;
                int unit = ks * 2 + b_unit_off;
                uint32_t off = row * 128 + ((unit ^ (row & 7)) << 4);
                ldsm4(bh[nh], Bh + off);
                ldsm4(bl[nh], Bl + off);
            }
#pragma unroll
            for (int mt = 0; mt < 4; ++mt) {
#pragma unroll
                for (int nt = 0; nt < 4; ++nt) {
                    const int nh = nt >> 1, p = (nt & 1) * 2;
                    mma_bf16(acc[mt][nt], ah[mt], bh[nh][p], bh[nh][p + 1]);
                    mma_bf16(acc[mt][nt], ah[mt], bl[nh][p], bl[nh][p + 1]);
                    mma_bf16(acc[mt][nt], al[mt], bh[nh][p], bh[nh][p + 1]);
                }
            }
        }
        CP_WAIT1();
        __syncthreads();
    }

    const int grow = lane >> 2;
    const int gcol = (lane & 3) * 2;
#pragma unroll
    for (int mt = 0; mt < 4; ++mt) {
#pragma unroll
        for (int nt = 0; nt < 4; ++nt) {
            const int m0 = bm + wm * 64 + mt * 16 + grow;
            const int n0 = bn + wn * 32 + nt * 8 + gcol;
            const float b0 = bias[n0], b1 = bias[n0 + 1];
            float v00 = acc[mt][nt][0] + b0, v01 = acc[mt][nt][1] + b1;
            float v10 = acc[mt][nt][2] + b0, v11 = acc[mt][nt][3] + b1;
            if (outf) {
                *(float2*)&outf[(size_t)m0 * D_MODEL + n0]       = make_float2(v00, v01);
                *(float2*)&outf[(size_t)(m0 + 8) * D_MODEL + n0] = make_float2(v10, v11);
            } else {
                __nv_bfloat16* ohi = ohiB + (size_t)z * MD;
                __nv_bfloat16* olo = oloB + (size_t)z * MD;
                *(uint32_t*)&ohi[(size_t)m0 * D_MODEL + n0] = pack_hi(v00, v01);
                *(uint32_t*)&olo[(size_t)m0 * D_MODEL + n0] =
                    pack_rn(v00 - hi_part(v00), v01 - hi_part(v01));
                *(uint32_t*)&ohi[(size_t)(m0 + 8) * D_MODEL + n0] = pack_hi(v10, v11);
                *(uint32_t*)&olo[(size_t)(m0 + 8) * D_MODEL + n0] =
                    pack_rn(v10 - hi_part(v10), v11 - hi_part(v11));
            }
        }
    }
}

// ---------------------------------------------------------------------------
// Causal flash attention on mma.sync, bf16 hi/lo split for QK^T and PV.
// Block: 128 queries, 8 warps. Key tiles of 64, 3-stage cp.async pipeline.
// Heavy (large-qb) blocks scheduled first via reversed block index.
// q/k/v are slots 0/1/2 of the projection arrays.
// ---------------------------------------------------------------------------
#define AQ 128
#define AKT 64
#define A_SQ_LO    16384
#define A_STAGES   32768
#define A_STAGE_SZ 32768
#define A_NSTAGE   3
#define A_SM_TOTAL (A_STAGES + A_NSTAGE * A_STAGE_SZ)   // 131072

__global__ __launch_bounds__(256, 1) void attn_mma(
    const __nv_bfloat16* __restrict__ prjhi, const __nv_bfloat16* __restrict__ prjlo,
    __nv_bfloat16* __restrict__ ohi, __nv_bfloat16* __restrict__ olo)
{
    extern __shared__ __align__(1024) char smem[];
    const uint32_t smem_base = smem_u32(smem);
    const int tid  = threadIdx.x;
    const int w    = tid >> 5;
    const int lane = tid & 31;
    const int qb = gridDim.x - 1 - blockIdx.x;   // heavy blocks first
    const int h  = blockIdx.y;
    const int b  = blockIdx.z;

    const __nv_bfloat16* qhi = prjhi;
    const __nv_bfloat16* qlo = prjlo;
    const __nv_bfloat16* khi = prjhi + MD;
    const __nv_bfloat16* klo = prjlo + MD;
    const __nv_bfloat16* vhi = prjhi + 2 * MD;
    const __nv_bfloat16* vlo = prjlo + 2 * MD;

    const int a_row_off  = ((lane >> 3) & 1) * 8 + (lane & 7);
    const int a_unit_off = lane >> 4;
    const int b_row_off  = ((lane >> 4) & 1) * 8 + (lane & 7);
    const int b_unit_off = (lane >> 3) & 1;
    const int grow = lane >> 2;
    const int gcol = (lane & 3) * 2;

    const int KT = 2 * qb + 2;

    auto q_load = [&]() {
#pragma unroll
        for (int i = 0; i < 8; ++i) {
            int idx = i * 256 + tid;
            int t = idx >> 10, row = (idx >> 3) & 127, u = idx & 7;
            const __nv_bfloat16* src =
                (t ? qlo : qhi) + (size_t)(b * SEQ + qb * AQ + row) * D_MODEL + h * DK + u * 8;
            uint32_t dst = smem_base + t * 16384 + row * 128 + ((u ^ (row & 7)) << 4);
            CP_ASYNC16(dst, src);
        }
        CP_COMMIT();
    };
    auto stage_load = [&](int s, int kt) {
        const uint32_t base = smem_base + A_STAGES + s * A_STAGE_SZ;
#pragma unroll
        for (int i = 0; i < 8; ++i) {
            int idx = i * 256 + tid;
            int t = idx >> 9, row = (idx >> 3) & 63, u = idx & 7;
            const __nv_bfloat16* arr = (t == 0) ? khi : (t == 1) ? klo : (t == 2) ? vhi : vlo;
            const __nv_bfloat16* src =
                arr + (size_t)(b * SEQ + kt * AKT + row) * D_MODEL + h * DK + u * 8;
            uint32_t dst = base + t * 8192 + row * 128 + ((u ^ (row & 7)) << 4);
            CP_ASYNC16(dst, src);
        }
        CP_COMMIT();
    };

    q_load();
    stage_load(0, 0);
    stage_load(1, 1);
    CP_WAIT1();
    __syncthreads();

    uint32_t qh[4][4], ql[4][4];
#pragma unroll
    for (int ks = 0; ks < 4; ++ks) {
        int row  = w * 16 + a_row_off;
        int unit = ks * 2 + a_unit_off;
        uint32_t off = row * 128 + ((unit ^ (row & 7)) << 4);
        ldsm4(qh[ks], smem_base + off);
        ldsm4(ql[ks], smem_base + A_SQ_LO + off);
    }

    float of[8][4];
#pragma unroll
    for (int nt = 0; nt < 8; ++nt)
#pragma unroll
        for (int j = 0; j < 4; ++j) of[nt][j] = 0.f;
    float m0 = -1e30f, m1 = -1e30f, l0 = 0.f, l1 = 0.f;

    const int q0g = qb * AQ + w * 16 + grow;
    const int q1g = q0g + 8;
    const int qmax_warp = qb * AQ + w * 16 + 15;
    const float NEG_INF = __int_as_float(0xff800000);

#pragma unroll 1
    for (int kt = 0; kt < KT; ++kt) {
        if (kt + 2 < KT) stage_load((kt + 2) % A_NSTAGE, kt + 2);
        else             CP_COMMIT();

        if (kt * AKT <= qmax_warp) {
            const uint32_t Kh = smem_base + A_STAGES + (kt % A_NSTAGE) * A_STAGE_SZ;
            const uint32_t Kl = Kh + 8192;
            const uint32_t Vh = Kh + 16384;
            const uint32_t Vl = Kh + 24576;

            // ---- S = Q K^T (3-term split) ----
            float sf[8][4];
#pragma unroll
            for (int nt = 0; nt < 8; ++nt)
#pragma unroll
                for (int j = 0; j < 4; ++j) sf[nt][j] = 0.f;

#pragma unroll
            for (int ks = 0; ks < 4; ++ks) {
#pragma unroll
                for (int nh = 0; nh < 4; ++nh) {
                    int row  = nh * 16 + b_row_off;
                    int unit = ks * 2 + b_unit_off;
                    uint32_t off = row * 128 + ((unit ^ (row & 7)) << 4);
                    uint32_t kh[4], kl[4];
                    ldsm4(kh, Kh + off);
                    ldsm4(kl, Kl + off);
                    mma_bf16(sf[2 * nh],     qh[ks], kh[0], kh[1]);
                    mma_bf16(sf[2 * nh],     qh[ks], kl[0], kl[1]);
                    mma_bf16(sf[2 * nh],     ql[ks], kh[0], kh[1]);
                    mma_bf16(sf[2 * nh + 1], qh[ks], kh[2], kh[3]);
                    mma_bf16(sf[2 * nh + 1], qh[ks], kl[2], kl[3]);
                    mma_bf16(sf[2 * nh + 1], ql[ks], kh[2], kh[3]);
                }
            }

            // ---- scale + causal mask ----
            const bool needmask = (kt >= 2 * qb);
#pragma unroll
            for (int nt = 0; nt < 8; ++nt) {
#pragma unroll
                for (int j = 0; j < 4; ++j) sf[nt][j] *= 0.125f;
                if (needmask) {
                    int c0 = kt * AKT + nt * 8 + gcol;
                    if (c0     > q0g) sf[nt][0] = NEG_INF;
                    if (c0 + 1 > q0g) sf[nt][1] = NEG_INF;
                    if (c0     > q1g) sf[nt][2] = NEG_INF;
                    if (c0 + 1 > q1g) sf[nt][3] = NEG_INF;
                }
            }

            // ---- online softmax ----
            float tm0 = sf[0][0], tm1 = sf[0][2];
#pragma unroll
            for (int nt = 0; nt < 8; ++nt) {
                tm0 = fmaxf(tm0, fmaxf(sf[nt][0], sf[nt][1]));
                tm1 = fmaxf(tm1, fmaxf(sf[nt][2], sf[nt][3]));
            }
            tm0 = fmaxf(tm0, __shfl_xor_sync(0xffffffffu, tm0, 1));
            tm0 = fmaxf(tm0, __shfl_xor_sync(0xffffffffu, tm0, 2));
            tm1 = fmaxf(tm1, __shfl_xor_sync(0xffffffffu, tm1, 1));
            tm1 = fmaxf(tm1, __shfl_xor_sync(0xffffffffu, tm1, 2));

            const float m0n = fmaxf(m0, tm0);
            const float m1n = fmaxf(m1, tm1);
            const float sc0 = __expf(m0 - m0n);
            const float sc1 = __expf(m1 - m1n);
            l0 *= sc0; l1 *= sc1;
#pragma unroll
            for (int nt = 0; nt < 8; ++nt) {
                of[nt][0] *= sc0; of[nt][1] *= sc0;
                of[nt][2] *= sc1; of[nt][3] *= sc1;
            }
            m0 = m0n; m1 = m1n;

            float p[8][4];
#pragma unroll
            for (int nt = 0; nt < 8; ++nt) {
                p[nt][0] = __expf(sf[nt][0] - m0n);
                p[nt][1] = __expf(sf[nt][1] - m0n);
                p[nt][2] = __expf(sf[nt][2] - m1n);
                p[nt][3] = __expf(sf[nt][3] - m1n);
                l0 += p[nt][0] + p[nt][1];
                l1 += p[nt][2] + p[nt][3];
            }

            // ---- pack P into A-frags ----
            uint32_t pah[4][4], pal[4][4];
#pragma unroll
            for (int j = 0; j < 4; ++j) {
                pah[j][0] = pack_hi(p[2 * j][0],     p[2 * j][1]);
                pah[j][1] = pack_hi(p[2 * j][2],     p[2 * j][3]);
                pah[j][2] = pack_hi(p[2 * j + 1][0], p[2 * j + 1][1]);
                pah[j][3] = pack_hi(p[2 * j + 1][2], p[2 * j + 1][3]);
                pal[j][0] = pack_rn(p[2 * j][0] - hi_part(p[2 * j][0]),
                                    p[2 * j][1] - hi_part(p[2 * j][1]));
                pal[j][1] = pack_rn(p[2 * j][2] - hi_part(p[2 * j][2]),
                                    p[2 * j][3] - hi_part(p[2 * j][3]));
                pal[j][2] = pack_rn(p[2 * j + 1][0] - hi_part(p[2 * j + 1][0]),
                                    p[2 * j + 1][1] - hi_part(p[2 * j + 1][1]));
                pal[j][3] = pack_rn(p[2 * j + 1][2] - hi_part(p[2 * j + 1][2]),
                                    p[2 * j + 1][3] - hi_part(p[2 * j + 1][3]));
            }

            // ---- O += P V (3-term split), V via ldmatrix.trans ----
            const int vrow_off = ((lane >> 3) & 1) * 8 + (lane & 7);
            const int vunit_off = (lane >> 4) & 1;
#pragma unroll
            for (int ks = 0; ks < 4; ++ks) {
#pragma unroll
                for (int nh = 0; nh < 4; ++nh) {
                    int row  = ks * 16 + vrow_off;
                    int unit = nh * 2 + vunit_off;
                    uint32_t off = row * 128 + ((unit ^ (row & 7)) << 4);
                    uint32_t vh[4], vl[4];
                    ldsm4t(vh, Vh + off);
                    ldsm4t(vl, Vl + off);
                    mma_bf16(of[2 * nh],     pah[ks], vh[0], vh[1]);
                    mma_bf16(of[2 * nh],     pah[ks], vl[0], vl[1]);
                    mma_bf16(of[2 * nh],     pal[ks], vh[0], vh[1]);
                    mma_bf16(of[2 * nh + 1], pah[ks], vh[2], vh[3]);
                    mma_bf16(of[2 * nh + 1], pah[ks], vl[2], vl[3]);
                    mma_bf16(of[2 * nh + 1], pal[ks], vh[2], vh[3]);
                }
            }
        }
        CP_WAIT1();
        __syncthreads();
    }

    // ---- epilogue ----
    l0 += __shfl_xor_sync(0xffffffffu, l0, 1);
    l0 += __shfl_xor_sync(0xffffffffu, l0, 2);
    l1 += __shfl_xor_sync(0xffffffffu, l1, 1);
    l1 += __shfl_xor_sync(0xffffffffu, l1, 2);
    const float inv0 = 1.f / l0;
    const float inv1 = 1.f / l1;

    const size_t r0 = (size_t)(b * SEQ + q0g);
    const size_t r1 = (size_t)(b * SEQ + q1g);
#pragma unroll
    for (int nt = 0; nt < 8; ++nt) {
        const int col = h * DK + nt * 8 + gcol;
        float v00 = of[nt][0] * inv0, v01 = of[nt][1] * inv0;
        float v10 = of[nt][2] * inv1, v11 = of[nt][3] * inv1;
        *(uint32_t*)&ohi[r0 * D_MODEL + col] = pack_hi(v00, v01);
        *(uint32_t*)&olo[r0 * D_MODEL + col] =
            pack_rn(v00 - hi_part(v00), v01 - hi_part(v01));
        *(uint32_t*)&ohi[r1 * D_MODEL + col] = pack_hi(v10, v11);
        *(uint32_t*)&olo[r1 * D_MODEL + col] =
            pack_rn(v10 - hi_part(v10), v11 - hi_part(v11));
    }
}

// ---------------------------------------------------------------------------
// Launch
// Inputs (metadata order): Q, K, V, mask, W_q, b_q, W_k, b_k, W_v, b_v, W_o, b_o
// ---------------------------------------------------------------------------
extern "C" void kernel_launch(void* const* d_in, const int* in_sizes, int n_in,
                              void* d_out, int out_size)
{
    const float* Q   = (const float*)d_in[0];
    const float* K   = (const float*)d_in[1];
    const float* V   = (const float*)d_in[2];
    const float* W_q = (const float*)d_in[4];
    const float* b_q = (const float*)d_in[5];
    const float* W_k = (const float*)d_in[6];
    const float* b_k = (const float*)d_in[7];
    const float* W_v = (const float*)d_in[8];
    const float* b_v = (const float*)d_in[9];
    const float* W_o = (const float*)d_in[10];
    const float* b_o = (const float*)d_in[11];
    float* out = (float*)d_out;

    __nv_bfloat16 *inhi, *inlo, *prjhi, *prjlo, *whi4, *wlo4;
    cudaGetSymbolAddress((void**)&inhi,  g_inhi);
    cudaGetSymbolAddress((void**)&inlo,  g_inlo);
    cudaGetSymbolAddress((void**)&prjhi, g_prjhi);
    cudaGetSymbolAddress((void**)&prjlo, g_prjlo);
    cudaGetSymbolAddress((void**)&whi4,  g_whi4);
    cudaGetSymbolAddress((void**)&wlo4,  g_wlo4);

    cudaFuncSetAttribute(gemm_mma, cudaFuncAttributeMaxDynamicSharedMemorySize, SM_TOTAL);
    cudaFuncSetAttribute(attn_mma, cudaFuncAttributeMaxDynamicSharedMemorySize, A_SM_TOTAL);

    const int nX4 = M_TOTAL * D_MODEL / 4;
    const int nW4 = D_MODEL * D_MODEL / 4;
    const int SPLIT_B = 256;

    // 1) all weight splits (one launch, z = W_q, W_k, W_v, W_o)
    dim3 gW((nW4 + SPLIT_B - 1) / SPLIT_B, 1, 4);
    split4_kernel<<<gW, SPLIT_B>>>(W_q, W_k, W_v, W_o, whi4, wlo4, nW4);

    // 2) all activation splits (one launch, z = Q, K, V)
    dim3 gX((nX4 + SPLIT_B - 1) / SPLIT_B, 1, 3);
    split3_kernel<<<gX, SPLIT_B>>>(Q, K, V, inhi, inlo, nX4);

    // 3) fused Q/K/V projections (one launch, 1536 CTAs)
    dim3 gQKV(D_MODEL / TN, M_TOTAL / TM, 3);
    gemm_mma<<<gQKV, 256, SM_TOTAL>>>(inhi, inlo, whi4, wlo4,
                                      b_q, b_k, b_v,
                                      nullptr, prjhi, prjlo);

    // 4) attention -> writes into input slot 0 (O-projection input)
    dim3 gAttn(SEQ / AQ, N_HEADS, BATCH);     // (16, 16, 4)
    attn_mma<<<gAttn, 256, A_SM_TOTAL>>>(prjhi, prjlo, inhi, inlo);

    // 5) O projection -> fp32 out (z = 0; weight slot 3 passed as base)
    dim3 gO(D_MODEL / TN, M_TOTAL / TM, 1);
    gemm_mma<<<gO, 256, SM_TOTAL>>>(inhi, inlo, whi4 + 3 * DD, wlo4 + 3 * DD,
                                    b_o, b_o, b_o,
                                    out, nullptr, nullptr);
}